// round 13
// baseline (speedup 1.0000x reference)
#include <cuda_runtime.h>
#include <cuda_fp16.h>
#include <math.h>
#include <stdint.h>

#define Hh 16
#define HS 64
#define E  1024
#define Tt 2048
#define Bq 4
#define BT (Bq*Tt)          // 8192
#define E3 (3*E)            // 3072
#define FE 4096
#define QSZ 4194304L        // one fragment bank (u32 count)

// ---------------- scratch ------------------------------------------------------
__device__ __align__(16) uint32_t g_hA  [(long)(BT/16) * 64  * 128];   // A-perm K=1024
__device__ __align__(16) uint32_t g_ff1A[(long)(BT/16) * 256 * 128];   // A-perm K=4096
__device__ __align__(16) uint32_t g_frag[6 * QSZ];   // Qhi|Qlo|Khi|Klo|Vhi|Vlo
__device__ __align__(16) float    g_x1  [(long)BT * E];
__device__ __align__(16) uint32_t g_wqkvB[(long)E/16  * (E3/8) * 64];
__device__ __align__(16) uint32_t g_wpB  [(long)E/16  * (E/8)  * 64];
__device__ __align__(16) uint32_t g_w1B  [(long)E/16  * (FE/8) * 64];
__device__ __align__(16) uint32_t g_w2B  [(long)FE/16 * (E/8)  * 64];

// ---------------- helpers ------------------------------------------------------
__device__ __forceinline__ uint32_t h2u(float a, float b) {
    __half2 h = __floats2half2_rn(a, b);
    return *(uint32_t*)&h;
}
__device__ __forceinline__ float flo(float x) {
    return x - __half2float(__float2half_rn(x));
}
// exp in the FMA pipe (no MUFU)
__device__ __forceinline__ float fexp(float x) {
    x = fmaxf(x, -87.0f);
    float y  = fmaf(x, 1.44269504f, 12582912.0f);
    float rn = y - 12582912.0f;
    float f  = fmaf(x, 1.44269504f, -rn);
    float p  =            1.33333588e-3f;
    p = fmaf(p, f, 9.61812910e-3f);
    p = fmaf(p, f, 5.55041087e-2f);
    p = fmaf(p, f, 2.40226507e-1f);
    p = fmaf(p, f, 6.93147181e-1f);
    p = fmaf(p, f, 1.0f);
    int n = (int)rn;
    return __int_as_float(__float_as_int(p) + (n << 23));
}
__device__ __forceinline__ void cpa16(uint32_t dst, const void* src) {
    asm volatile("cp.async.cg.shared.global [%0], [%1], 16;" :: "r"(dst), "l"(src));
}
#define CP_COMMIT() asm volatile("cp.async.commit_group;" ::: "memory")
#define CP_WAIT2()  asm volatile("cp.async.wait_group 2;" ::: "memory")
__device__ __forceinline__ uint32_t smem_u32(const void* p) {
    uint32_t a;
    asm("{ .reg .u64 t; cvta.to.shared.u64 t, %1; cvt.u32.u64 %0, t; }" : "=r"(a) : "l"(p));
    return a;
}
__device__ __forceinline__ void pfl1(const void* p) {
    asm volatile("prefetch.global.L1 [%0];" :: "l"(p));
}
#define MMA16816(c, a, b)                                                        \
    asm volatile("mma.sync.aligned.m16n8k16.row.col.f32.f16.f16.f32 "            \
                 "{%0,%1,%2,%3},{%4,%5,%6,%7},{%8,%9},{%0,%1,%2,%3};"            \
                 : "+f"(c[0]), "+f"(c[1]), "+f"(c[2]), "+f"(c[3])                 \
                 : "r"(a.x), "r"(a.y), "r"(a.z), "r"(a.w), "r"(b.x), "r"(b.y))

// ================= fp16 tensor GEMM, pre-permuted operands ======================
// CTA tile 128x128, 8 warps (2m x 4n), warp tile 64x32, K-iter = 16 (R9 config).
// MODE 0: fp32 C; 1: fp32 C+bias+res; 2: A-perm relu(C+bias); 3: QKV hi/lo frags
template<int MODE>
__global__ __launch_bounds__(256) void hgemm(
    const uint32_t* __restrict__ Aperm, const uint32_t* __restrict__ Bpk,
    const float* __restrict__ bias, const float* __restrict__ res,
    void* __restrict__ Cout, int KD16, int N, int KD16out)
{
    __shared__ __align__(16) uint8_t smArr[4 * 8192];
    uint32_t sb = smem_u32(smArr);
    const int tid = threadIdx.x;
    const int ln = tid & 31, wid = tid >> 5;
    const int warp_m = wid & 1, warp_n = wid >> 1;
    const int m0 = blockIdx.y * 128, n0 = blockIdx.x * 128;
    const int NBt = N >> 3;
    const int nb0 = n0 >> 3;

    const char* Ag = (const char*)Aperm;
    const char* Bg = (const char*)Bpk;
    const int a_mb = tid >> 5;
    const int b_nbt = tid >> 4, b_q = tid & 15;

    auto load_stage = [&](int c) {
        int s = c & 3;
        cpa16(sb + s * 8192 + a_mb * 512 + ln * 16,
              Ag + (((long)(m0 / 16 + a_mb) * KD16 + c) * 512) + ln * 16);
        cpa16(sb + s * 8192 + 4096 + b_nbt * 256 + b_q * 16,
              Bg + (((long)c * NBt + nb0 + b_nbt) * 256) + b_q * 16);
        CP_COMMIT();
    };

    float acc[4][4][4];
    #pragma unroll
    for (int i = 0; i < 4; i++)
        #pragma unroll
        for (int j = 0; j < 4; j++)
            #pragma unroll
            for (int e = 0; e < 4; e++) acc[i][j][e] = 0.f;

    load_stage(0); load_stage(1); load_stage(2);

    for (int c = 0; c < KD16; c++) {
        CP_WAIT2();
        __syncthreads();
        int pc = c + 3;
        if (pc < KD16) load_stage(pc); else CP_COMMIT();

        uint32_t as = sb + (c & 3) * 8192;
        uint32_t bs = as + 4096;
        uint4 af[4];
        uint2 bf[4];
        #pragma unroll
        for (int mt = 0; mt < 4; mt++)
            asm volatile("ld.shared.v4.u32 {%0,%1,%2,%3}, [%4];"
                : "=r"(af[mt].x), "=r"(af[mt].y), "=r"(af[mt].z), "=r"(af[mt].w)
                : "r"(as + (warp_m * 4 + mt) * 512 + ln * 16));
        #pragma unroll
        for (int nt = 0; nt < 4; nt++)
            asm volatile("ld.shared.v2.u32 {%0,%1}, [%2];"
                : "=r"(bf[nt].x), "=r"(bf[nt].y)
                : "r"(bs + (warp_n * 4 + nt) * 256 + ln * 8));
        #pragma unroll
        for (int mt = 0; mt < 4; mt++)
            #pragma unroll
            for (int nt = 0; nt < 4; nt++)
                MMA16816(acc[mt][nt], af[mt], bf[nt]);
        __syncthreads();
    }

    const int g = ln >> 2, tg = ln & 3;
    const int row_base = m0 + warp_m * 64;
    const int col_base = n0 + warp_n * 32;
    #pragma unroll
    for (int mt = 0; mt < 4; mt++) {
        #pragma unroll
        for (int nt = 0; nt < 4; nt++) {
            int r0 = row_base + mt * 16 + g;
            int c0 = col_base + nt * 8 + tg * 2;
            float v00 = acc[mt][nt][0], v01 = acc[mt][nt][1];
            float v10 = acc[mt][nt][2], v11 = acc[mt][nt][3];
            if (MODE == 1 || MODE == 2) {
                float b0 = bias[c0], b1 = bias[c0 + 1];
                v00 += b0; v01 += b1; v10 += b0; v11 += b1;
            }
            if (MODE == 0 || MODE == 1) {
                float* C = (float*)Cout;
                long off0 = (long)r0 * N + c0;
                long off1 = (long)(r0 + 8) * N + c0;
                if (MODE == 1) {
                    float2 rv0 = *(const float2*)(res + off0);
                    float2 rv1 = *(const float2*)(res + off1);
                    v00 += rv0.x; v01 += rv0.y; v10 += rv1.x; v11 += rv1.y;
                }
                *(float2*)(C + off0) = make_float2(v00, v01);
                *(float2*)(C + off1) = make_float2(v10, v11);
            } else if (MODE == 2) {
                v00 = fmaxf(v00, 0.f); v01 = fmaxf(v01, 0.f);
                v10 = fmaxf(v10, 0.f); v11 = fmaxf(v11, 0.f);
                uint32_t* Ao = (uint32_t*)Cout;
                int kc = c0 >> 4;
                int i2b = ((c0 & 15) >= 8) ? 2 : 0;
                int lane_p = (g & 7) * 4 + ((c0 & 7) >> 1);
                long base0 = ((long)(r0 >> 4) * KD16out + kc) * 128 + lane_p * 4;
                Ao[base0 + i2b]     = h2u(v00, v01);
                Ao[base0 + i2b + 1] = h2u(v10, v11);
            } else {
                uint32_t* F = (uint32_t*)Cout;
                int sct = c0 >> 10;
                int hh  = (c0 >> 6) & 15;
                int d   = c0 & 63;
                int b   = r0 >> 11;
                int t   = r0 & 2047;
                int bh  = b * 16 + hh;
                if (sct == 0) {
                    long off = (((long)(bh * 128 + (t >> 4)) * 4 + (d >> 4)) << 7)
                             + ((t & 7) * 4 + ((d & 7) >> 1)) * 4
                             + (((d & 15) >= 8) ? 2 : 0);
                    F[off]           = h2u(v00, v01);
                    F[off + 1]       = h2u(v10, v11);
                    F[QSZ + off]     = h2u(flo(v00), flo(v01));
                    F[QSZ + off + 1] = h2u(flo(v10), flo(v11));
                } else if (sct == 1) {
                    int ln2 = (t & 7) * 4 + ((d & 7) >> 1);
                    int j = ((d & 15) >= 8) ? 1 : 0;
                    long off = ((long)(bh * 256 + (t >> 3)) * 4 + (d >> 4)) * 64 + ln2 * 2 + j;
                    F[2*QSZ + off]       = h2u(v00, v01);
                    F[2*QSZ + off + 256] = h2u(v10, v11);
                    F[3*QSZ + off]       = h2u(flo(v00), flo(v01));
                    F[3*QSZ + off + 256] = h2u(flo(v10), flo(v11));
                } else {
                    float p00 = __shfl_xor_sync(0xffffffffu, v00, 4);
                    float p01 = __shfl_xor_sync(0xffffffffu, v01, 4);
                    float p10 = __shfl_xor_sync(0xffffffffu, v10, 4);
                    float p11 = __shfl_xor_sync(0xffffffffu, v11, 4);
                    if (!(g & 1)) {
                        int vl2 = (d & 7) * 4 + (g >> 1);
                        long off = ((long)(bh * 128 + (t >> 4)) * 8 + (d >> 3)) * 64 + vl2 * 2;
                        F[4*QSZ + off]     = h2u(v00, p00);
                        F[4*QSZ + off + 1] = h2u(v10, p10);
                        F[4*QSZ + off + 8] = h2u(v01, p01);
                        F[4*QSZ + off + 9] = h2u(v11, p11);
                        F[5*QSZ + off]     = h2u(flo(v00), flo(p00));
                        F[5*QSZ + off + 1] = h2u(flo(v10), flo(p10));
                        F[5*QSZ + off + 8] = h2u(flo(v01), flo(p01));
                        F[5*QSZ + off + 9] = h2u(flo(v11), flo(p11));
                    }
                }
            }
        }
    }
}

// ---------------- LayerNorm -> A-perm -------------------------------------------
__device__ __forceinline__ float block_sum_256(float v, float* red) {
    #pragma unroll
    for (int o = 16; o > 0; o >>= 1) v += __shfl_xor_sync(0xffffffffu, v, o);
    int lane = threadIdx.x & 31, w = threadIdx.x >> 5;
    if (lane == 0) red[w] = v;
    __syncthreads();
    float r = (threadIdx.x < 8) ? red[threadIdx.x] : 0.f;
    if (w == 0) {
        #pragma unroll
        for (int o = 4; o > 0; o >>= 1) r += __shfl_xor_sync(0xffu, r, o);
        if (lane == 0) red[0] = r;
    }
    __syncthreads();
    float out = red[0];
    __syncthreads();
    return out;
}

__global__ void ln_pack(const float* __restrict__ x, const float* __restrict__ gain,
                        const float* __restrict__ bias, uint32_t* __restrict__ o) {
    __shared__ float red[8];
    long row = blockIdx.x;
    int tid = threadIdx.x;
    float4 v = ((const float4*)(x + row * E))[tid];
    float mean = block_sum_256(v.x + v.y + v.z + v.w, red) * (1.0f / E);
    float dx = v.x-mean, dy = v.y-mean, dz = v.z-mean, dw = v.w-mean;
    float var = block_sum_256(dx*dx + dy*dy + dz*dz + dw*dw, red) * (1.0f/(E-1));
    float inv = 1.0f / sqrtf(var + 1e-5f);
    float4 gv = ((const float4*)gain)[tid];
    float4 bv = ((const float4*)bias)[tid];
    float r0 = dx*inv*gv.x + bv.x, r1 = dy*inv*gv.y + bv.y;
    float r2 = dz*inv*gv.z + bv.z, r3 = dw*inv*gv.w + bv.w;
    int r = (int)(row & 15);
    long mbG = row >> 4;
    int kc = tid >> 2, kk0 = (tid & 3) * 4;
    int i2 = (r >= 8 ? 1 : 0) + (kk0 >= 8 ? 2 : 0);
    int lane = (r & 7) * 4 + ((kk0 & 7) >> 1);
    long base = (mbG * 64 + kc) * 128;
    o[base + lane * 4 + i2]       = h2u(r0, r1);
    o[base + (lane + 1) * 4 + i2] = h2u(r2, r3);
}

// ---------------- B pack kernels --------------------------------------------------
__global__ void pack_w(const float* __restrict__ W, int N, long total,
                       uint32_t* __restrict__ out) {
    long idx = (long)blockIdx.x * 256 + threadIdx.x;
    if (idx >= total) return;
    int j = idx & 1;
    int lane = (idx >> 1) & 31;
    long rest = idx >> 6;
    int NBt = N >> 3;
    int nb = (int)(rest % NBt);
    int kc = (int)(rest / NBt);
    int n = nb * 8 + (lane >> 2);
    int k = kc * 16 + j * 8 + (lane & 3) * 2;
    out[idx] = h2u(W[(long)k * N + n], W[(long)(k + 1) * N + n]);
}
__global__ void pack_qkv(const float* __restrict__ Wq, const float* __restrict__ Wk,
                         const float* __restrict__ Wv, uint32_t* __restrict__ out) {
    long idx = (long)blockIdx.x * 256 + threadIdx.x;
    if (idx >= (long)(E/16) * (E3/8) * 64) return;
    int j = idx & 1;
    int lane = (idx >> 1) & 31;
    long rest = idx >> 6;
    int nb = (int)(rest % (E3/8));
    int kc = (int)(rest / (E3/8));
    int n = nb * 8 + (lane >> 2);
    int k = kc * 16 + j * 8 + (lane & 3) * 2;
    int s = n >> 10, rr = n & 1023, h = rr >> 6, d = rr & 63;
    const float* W = (s == 0) ? Wq : (s == 1) ? Wk : Wv;
    long o1 = (long)h * (E * HS) + (long)k * HS + d;
    out[idx] = h2u(W[o1], W[o1 + HS]);
}

// ---------------- MMA flash attention: 128 q-rows/block, 8 warps ------------------
// grid (16, 64), 256 threads. Per-warp causal bound ktmax = 2*qt + (wq>>2).
__global__ __launch_bounds__(256, 2) void attn_mma(const uint32_t* __restrict__ pf,
                                                   uint32_t* __restrict__ out) {
    const int qt = 15 - blockIdx.x;
    const int bh = blockIdx.y;
    const int ln = threadIdx.x & 31, wq = threadIdx.x >> 5;   // wq in 0..7
    const int g = ln >> 2, tg = ln & 3;
    const int row0 = qt * 128 + wq * 16 + g;
    const int ktmax = 2 * qt + (wq >> 2);

    uint4 qh[4], qlo[4];
    const uint32_t* qfb = pf + ((long)(bh * 128 + qt * 8 + wq) * 4) * 128 + ln * 4;
    #pragma unroll
    for (int kc = 0; kc < 4; kc++) {
        qh[kc]  = *(const uint4*)(qfb + kc * 128);
        qlo[kc] = *(const uint4*)(qfb + QSZ + kc * 128);
    }

    float oc[8][4];
    #pragma unroll
    for (int i = 0; i < 8; i++) { oc[i][0]=oc[i][1]=oc[i][2]=oc[i][3]=0.f; }
    float m0 = -1e30f, m1 = -1e30f, l0 = 0.f, l1 = 0.f;

    for (int kt = 0; kt <= ktmax; kt++) {
        // prefetch next-kt K/V fragments into L1
        if (kt < ktmax) {
            const uint32_t* kn = pf + 2*QSZ + ((long)(bh * 256 + (kt + 1) * 8) * 4) * 64;
            const uint32_t* vn = pf + 4*QSZ + ((long)(bh * 128 + (kt + 1) * 4) * 8) * 64;
            pfl1(kn + ln * 64);            pfl1(kn + ln * 64 + 32);
            pfl1(kn + QSZ + ln * 64);      pfl1(kn + QSZ + ln * 64 + 32);
            pfl1(vn + ln * 64);            pfl1(vn + ln * 64 + 32);
            pfl1(vn + QSZ + ln * 64);      pfl1(vn + QSZ + ln * 64 + 32);
        }

        float sc[8][4];
        #pragma unroll
        for (int i = 0; i < 8; i++) { sc[i][0]=sc[i][1]=sc[i][2]=sc[i][3]=0.f; }

        const uint32_t* kfb = pf + 2*QSZ + ((long)(bh * 256 + kt * 8) * 4) * 64 + ln * 2;
        #pragma unroll
        for (int kc = 0; kc < 4; kc++)
            #pragma unroll
            for (int nt = 0; nt < 8; nt++) {
                uint2 kbh = *(const uint2*)(kfb + (nt * 4 + kc) * 64);
                uint2 kbl = *(const uint2*)(kfb + QSZ + (nt * 4 + kc) * 64);
                MMA16816(sc[nt], qh[kc],  kbh);
                MMA16816(sc[nt], qlo[kc], kbh);
                MMA16816(sc[nt], qh[kc],  kbl);
            }

        if (kt == ktmax) {
            #pragma unroll
            for (int nt = 0; nt < 8; nt++) {
                int c = kt * 64 + nt * 8 + tg * 2;
                sc[nt][0] = (c     > row0)     ? -1e30f : sc[nt][0] * 8.f;
                sc[nt][1] = (c + 1 > row0)     ? -1e30f : sc[nt][1] * 8.f;
                sc[nt][2] = (c     > row0 + 8) ? -1e30f : sc[nt][2] * 8.f;
                sc[nt][3] = (c + 1 > row0 + 8) ? -1e30f : sc[nt][3] * 8.f;
            }
        } else {
            #pragma unroll
            for (int nt = 0; nt < 8; nt++) {
                sc[nt][0] *= 8.f; sc[nt][1] *= 8.f; sc[nt][2] *= 8.f; sc[nt][3] *= 8.f;
            }
        }

        float mx0 = m0, mx1 = m1;
        #pragma unroll
        for (int nt = 0; nt < 8; nt++) {
            mx0 = fmaxf(mx0, fmaxf(sc[nt][0], sc[nt][1]));
            mx1 = fmaxf(mx1, fmaxf(sc[nt][2], sc[nt][3]));
        }
        mx0 = fmaxf(mx0, __shfl_xor_sync(0xffffffffu, mx0, 1));
        mx0 = fmaxf(mx0, __shfl_xor_sync(0xffffffffu, mx0, 2));
        mx1 = fmaxf(mx1, __shfl_xor_sync(0xffffffffu, mx1, 1));
        mx1 = fmaxf(mx1, __shfl_xor_sync(0xffffffffu, mx1, 2));
        float corr0 = fexp(m0 - mx0), corr1 = fexp(m1 - mx1);
        m0 = mx0; m1 = mx1;
        l0 *= corr0; l1 *= corr1;
        #pragma unroll
        for (int nt = 0; nt < 8; nt++) {
            sc[nt][0] = fexp(sc[nt][0] - mx0);
            sc[nt][1] = fexp(sc[nt][1] - mx0);
            sc[nt][2] = fexp(sc[nt][2] - mx1);
            sc[nt][3] = fexp(sc[nt][3] - mx1);
            l0 += sc[nt][0] + sc[nt][1];
            l1 += sc[nt][2] + sc[nt][3];
        }
        uint4 pah[4], pal[4];
        #pragma unroll
        for (int k2 = 0; k2 < 4; k2++) {
            pah[k2].x = h2u(sc[2*k2][0],   sc[2*k2][1]);
            pah[k2].y = h2u(sc[2*k2][2],   sc[2*k2][3]);
            pah[k2].z = h2u(sc[2*k2+1][0], sc[2*k2+1][1]);
            pah[k2].w = h2u(sc[2*k2+1][2], sc[2*k2+1][3]);
            pal[k2].x = h2u(flo(sc[2*k2][0]),   flo(sc[2*k2][1]));
            pal[k2].y = h2u(flo(sc[2*k2][2]),   flo(sc[2*k2][3]));
            pal[k2].z = h2u(flo(sc[2*k2+1][0]), flo(sc[2*k2+1][1]));
            pal[k2].w = h2u(flo(sc[2*k2+1][2]), flo(sc[2*k2+1][3]));
        }
        #pragma unroll
        for (int nbv = 0; nbv < 8; nbv++) {
            oc[nbv][0] *= corr0; oc[nbv][1] *= corr0;
            oc[nbv][2] *= corr1; oc[nbv][3] *= corr1;
        }
        const uint32_t* vfb = pf + 4*QSZ + ((long)(bh * 128 + kt * 4) * 8) * 64 + ln * 2;
        #pragma unroll
        for (int k2 = 0; k2 < 4; k2++)
            #pragma unroll
            for (int nbv = 0; nbv < 8; nbv++) {
                uint2 vbh = *(const uint2*)(vfb + (k2 * 8 + nbv) * 64);
                uint2 vbl = *(const uint2*)(vfb + QSZ + (k2 * 8 + nbv) * 64);
                MMA16816(oc[nbv], pah[k2], vbh);
                MMA16816(oc[nbv], pal[k2], vbh);
                MMA16816(oc[nbv], pah[k2], vbl);
            }
    }

    l0 += __shfl_xor_sync(0xffffffffu, l0, 1);
    l0 += __shfl_xor_sync(0xffffffffu, l0, 2);
    l1 += __shfl_xor_sync(0xffffffffu, l1, 1);
    l1 += __shfl_xor_sync(0xffffffffu, l1, 2);
    float inv0 = 1.f / l0, inv1 = 1.f / l1;

    int hloc = bh & 15;
    long mbG = (long)(bh >> 4) * 128 + qt * 8 + wq;
    #pragma unroll
    for (int nbv = 0; nbv < 8; nbv++) {
        int kco = hloc * 4 + (nbv >> 1);
        long base = (mbG * 64 + kco) * 128 + (g * 4 + tg) * 4 + ((nbv & 1) ? 2 : 0);
        out[base]     = h2u(oc[nbv][0] * inv0, oc[nbv][1] * inv0);
        out[base + 1] = h2u(oc[nbv][2] * inv1, oc[nbv][3] * inv1);
    }
}

// ---------------- launch ----------------------------------------------------------
extern "C" void kernel_launch(void* const* d_in, const int* in_sizes, int n_in,
                              void* d_out, int out_size) {
    const float* x   = (const float*)d_in[0];
    const float* Wq  = (const float*)d_in[1];
    const float* Wk  = (const float*)d_in[2];
    const float* Wv  = (const float*)d_in[3];
    const float* Wp  = (const float*)d_in[4];
    const float* bp  = (const float*)d_in[5];
    const float* W1  = (const float*)d_in[6];
    const float* b1  = (const float*)d_in[7];
    const float* W2  = (const float*)d_in[8];
    const float* b2  = (const float*)d_in[9];
    const float* g1  = (const float*)d_in[10];
    const float* be1 = (const float*)d_in[11];
    const float* g2  = (const float*)d_in[12];
    const float* be2 = (const float*)d_in[13];
    float* out = (float*)d_out;

    uint32_t *phA, *pff1A, *pfrag, *pwqkvB, *pwpB, *pw1B, *pw2B;
    float *px1;
    cudaGetSymbolAddress((void**)&phA,    g_hA);
    cudaGetSymbolAddress((void**)&pff1A,  g_ff1A);
    cudaGetSymbolAddress((void**)&pfrag,  g_frag);
    cudaGetSymbolAddress((void**)&px1,    g_x1);
    cudaGetSymbolAddress((void**)&pwqkvB, g_wqkvB);
    cudaGetSymbolAddress((void**)&pwpB,   g_wpB);
    cudaGetSymbolAddress((void**)&pw1B,   g_w1B);
    cudaGetSymbolAddress((void**)&pw2B,   g_w2B);

    long tq = (long)(E/16) * (E3/8) * 64;
    pack_qkv<<<(int)((tq + 255) / 256), 256>>>(Wq, Wk, Wv, pwqkvB);
    long tp = (long)(E/16) * (E/8) * 64;
    pack_w<<<(int)((tp + 255) / 256), 256>>>(Wp, E, tp, pwpB);
    long t1 = (long)(E/16) * (FE/8) * 64;
    pack_w<<<(int)((t1 + 255) / 256), 256>>>(W1, FE, t1, pw1B);
    long t2 = (long)(FE/16) * (E/8) * 64;
    pack_w<<<(int)((t2 + 255) / 256), 256>>>(W2, E, t2, pw2B);

    // LN1 -> A-perm
    ln_pack<<<BT, 256>>>(x, g1, be1, phA);
    // qkv = h @ Wqkv -> Q/K/V hi+lo fragments
    hgemm<3><<<dim3(E3/128, BT/128), 256>>>(phA, pwqkvB, nullptr, nullptr, pfrag, 64, E3, 0);
    // attention -> A-perm
    attn_mma<<<dim3(16, 64), 256>>>(pfrag, phA);
    // x1 = x + attn @ Wp + bp
    hgemm<1><<<dim3(E/128, BT/128), 256>>>(phA, pwpB, bp, x, px1, 64, E, 0);
    // LN2 -> A-perm
    ln_pack<<<BT, 256>>>(px1, g2, be2, phA);
    // ff1 = relu(h2 @ W1 + b1) -> A-perm
    hgemm<2><<<dim3(FE/128, BT/128), 256>>>(phA, pw1B, b1, nullptr, pff1A, 64, FE, 256);
    // out = x1 + ff1 @ W2 + b2
    hgemm<1><<<dim3(E/128, BT/128), 256>>>(pff1A, pw2B, b2, px1, out, 256, E, 0);
}

// round 15
// speedup vs baseline: 1.0354x; 1.0354x over previous
#include <cuda_runtime.h>
#include <cuda_fp16.h>
#include <math.h>
#include <stdint.h>

#define Hh 16
#define HS 64
#define E  1024
#define Tt 2048
#define Bq 4
#define BT (Bq*Tt)          // 8192
#define E3 (3*E)            // 3072
#define FE 4096
#define QSZ 4194304L        // one fragment bank (u32 count)

// ---------------- scratch ------------------------------------------------------
__device__ __align__(16) uint32_t g_hA  [(long)(BT/16) * 64  * 128];   // A-perm K=1024
__device__ __align__(16) uint32_t g_ff1A[(long)(BT/16) * 256 * 128];   // A-perm K=4096
__device__ __align__(16) uint32_t g_frag[6 * QSZ];   // Qhi|Qlo|Khi|Klo|Vhi|Vlo
__device__ __align__(16) float    g_x1  [(long)BT * E];
__device__ __align__(16) uint32_t g_wqkvB[(long)E/16  * (E3/8) * 64];
__device__ __align__(16) uint32_t g_wpB  [(long)E/16  * (E/8)  * 64];
__device__ __align__(16) uint32_t g_w1B  [(long)E/16  * (FE/8) * 64];
__device__ __align__(16) uint32_t g_w2B  [(long)FE/16 * (E/8)  * 64];

// ---------------- helpers ------------------------------------------------------
__device__ __forceinline__ uint32_t h2u(float a, float b) {
    __half2 h = __floats2half2_rn(a, b);
    return *(uint32_t*)&h;
}
__device__ __forceinline__ float flo(float x) {
    return x - __half2float(__float2half_rn(x));
}
// exp in the FMA pipe (no MUFU)
__device__ __forceinline__ float fexp(float x) {
    x = fmaxf(x, -87.0f);
    float y  = fmaf(x, 1.44269504f, 12582912.0f);
    float rn = y - 12582912.0f;
    float f  = fmaf(x, 1.44269504f, -rn);
    float p  =            1.33333588e-3f;
    p = fmaf(p, f, 9.61812910e-3f);
    p = fmaf(p, f, 5.55041087e-2f);
    p = fmaf(p, f, 2.40226507e-1f);
    p = fmaf(p, f, 6.93147181e-1f);
    p = fmaf(p, f, 1.0f);
    int n = (int)rn;
    return __int_as_float(__float_as_int(p) + (n << 23));
}
__device__ __forceinline__ void cpa16(uint32_t dst, const void* src) {
    asm volatile("cp.async.cg.shared.global [%0], [%1], 16;" :: "r"(dst), "l"(src));
}
#define CP_COMMIT() asm volatile("cp.async.commit_group;" ::: "memory")
#define CP_WAIT2()  asm volatile("cp.async.wait_group 2;" ::: "memory")
__device__ __forceinline__ uint32_t smem_u32(const void* p) {
    uint32_t a;
    asm("{ .reg .u64 t; cvta.to.shared.u64 t, %1; cvt.u32.u64 %0, t; }" : "=r"(a) : "l"(p));
    return a;
}
__device__ __forceinline__ void pfl1(const void* p) {
    asm volatile("prefetch.global.L1 [%0];" :: "l"(p));
}
#define MMA16816(c, a, b)                                                        \
    asm volatile("mma.sync.aligned.m16n8k16.row.col.f32.f16.f16.f32 "            \
                 "{%0,%1,%2,%3},{%4,%5,%6,%7},{%8,%9},{%0,%1,%2,%3};"            \
                 : "+f"(c[0]), "+f"(c[1]), "+f"(c[2]), "+f"(c[3])                 \
                 : "r"(a.x), "r"(a.y), "r"(a.z), "r"(a.w), "r"(b.x), "r"(b.y))

// ================= fp16 tensor GEMM, pre-permuted operands ======================
// CTA tile 128x128, 8 warps (2m x 4n), warp tile 64x32, K-iter = 16 (R9 config).
// MODE 0: fp32 C; 1: fp32 C+bias+res; 2: A-perm relu(C+bias); 3: QKV hi/lo frags
template<int MODE>
__global__ __launch_bounds__(256) void hgemm(
    const uint32_t* __restrict__ Aperm, const uint32_t* __restrict__ Bpk,
    const float* __restrict__ bias, const float* __restrict__ res,
    void* __restrict__ Cout, int KD16, int N, int KD16out)
{
    __shared__ __align__(16) uint8_t smArr[4 * 8192];
    uint32_t sb = smem_u32(smArr);
    const int tid = threadIdx.x;
    const int ln = tid & 31, wid = tid >> 5;
    const int warp_m = wid & 1, warp_n = wid >> 1;
    const int m0 = blockIdx.y * 128, n0 = blockIdx.x * 128;
    const int NBt = N >> 3;
    const int nb0 = n0 >> 3;

    const char* Ag = (const char*)Aperm;
    const char* Bg = (const char*)Bpk;
    const int a_mb = tid >> 5;
    const int b_nbt = tid >> 4, b_q = tid & 15;

    auto load_stage = [&](int c) {
        int s = c & 3;
        cpa16(sb + s * 8192 + a_mb * 512 + ln * 16,
              Ag + (((long)(m0 / 16 + a_mb) * KD16 + c) * 512) + ln * 16);
        cpa16(sb + s * 8192 + 4096 + b_nbt * 256 + b_q * 16,
              Bg + (((long)c * NBt + nb0 + b_nbt) * 256) + b_q * 16);
        CP_COMMIT();
    };

    float acc[4][4][4];
    #pragma unroll
    for (int i = 0; i < 4; i++)
        #pragma unroll
        for (int j = 0; j < 4; j++)
            #pragma unroll
            for (int e = 0; e < 4; e++) acc[i][j][e] = 0.f;

    load_stage(0); load_stage(1); load_stage(2);

    for (int c = 0; c < KD16; c++) {
        CP_WAIT2();
        __syncthreads();
        int pc = c + 3;
        if (pc < KD16) load_stage(pc); else CP_COMMIT();

        uint32_t as = sb + (c & 3) * 8192;
        uint32_t bs = as + 4096;
        uint4 af[4];
        uint2 bf[4];
        #pragma unroll
        for (int mt = 0; mt < 4; mt++)
            asm volatile("ld.shared.v4.u32 {%0,%1,%2,%3}, [%4];"
                : "=r"(af[mt].x), "=r"(af[mt].y), "=r"(af[mt].z), "=r"(af[mt].w)
                : "r"(as + (warp_m * 4 + mt) * 512 + ln * 16));
        #pragma unroll
        for (int nt = 0; nt < 4; nt++)
            asm volatile("ld.shared.v2.u32 {%0,%1}, [%2];"
                : "=r"(bf[nt].x), "=r"(bf[nt].y)
                : "r"(bs + (warp_n * 4 + nt) * 256 + ln * 8));
        #pragma unroll
        for (int mt = 0; mt < 4; mt++)
            #pragma unroll
            for (int nt = 0; nt < 4; nt++)
                MMA16816(acc[mt][nt], af[mt], bf[nt]);
        __syncthreads();
    }

    const int g = ln >> 2, tg = ln & 3;
    const int row_base = m0 + warp_m * 64;
    const int col_base = n0 + warp_n * 32;
    #pragma unroll
    for (int mt = 0; mt < 4; mt++) {
        #pragma unroll
        for (int nt = 0; nt < 4; nt++) {
            int r0 = row_base + mt * 16 + g;
            int c0 = col_base + nt * 8 + tg * 2;
            float v00 = acc[mt][nt][0], v01 = acc[mt][nt][1];
            float v10 = acc[mt][nt][2], v11 = acc[mt][nt][3];
            if (MODE == 1 || MODE == 2) {
                float b0 = bias[c0], b1 = bias[c0 + 1];
                v00 += b0; v01 += b1; v10 += b0; v11 += b1;
            }
            if (MODE == 0 || MODE == 1) {
                float* C = (float*)Cout;
                long off0 = (long)r0 * N + c0;
                long off1 = (long)(r0 + 8) * N + c0;
                if (MODE == 1) {
                    float2 rv0 = *(const float2*)(res + off0);
                    float2 rv1 = *(const float2*)(res + off1);
                    v00 += rv0.x; v01 += rv0.y; v10 += rv1.x; v11 += rv1.y;
                }
                *(float2*)(C + off0) = make_float2(v00, v01);
                *(float2*)(C + off1) = make_float2(v10, v11);
            } else if (MODE == 2) {
                v00 = fmaxf(v00, 0.f); v01 = fmaxf(v01, 0.f);
                v10 = fmaxf(v10, 0.f); v11 = fmaxf(v11, 0.f);
                uint32_t* Ao = (uint32_t*)Cout;
                int kc = c0 >> 4;
                int i2b = ((c0 & 15) >= 8) ? 2 : 0;
                int lane_p = (g & 7) * 4 + ((c0 & 7) >> 1);
                long base0 = ((long)(r0 >> 4) * KD16out + kc) * 128 + lane_p * 4;
                Ao[base0 + i2b]     = h2u(v00, v01);
                Ao[base0 + i2b + 1] = h2u(v10, v11);
            } else {
                uint32_t* F = (uint32_t*)Cout;
                int sct = c0 >> 10;
                int hh  = (c0 >> 6) & 15;
                int d   = c0 & 63;
                int b   = r0 >> 11;
                int t   = r0 & 2047;
                int bh  = b * 16 + hh;
                if (sct == 0) {
                    long off = (((long)(bh * 128 + (t >> 4)) * 4 + (d >> 4)) << 7)
                             + ((t & 7) * 4 + ((d & 7) >> 1)) * 4
                             + (((d & 15) >= 8) ? 2 : 0);
                    F[off]           = h2u(v00, v01);
                    F[off + 1]       = h2u(v10, v11);
                    F[QSZ + off]     = h2u(flo(v00), flo(v01));
                    F[QSZ + off + 1] = h2u(flo(v10), flo(v11));
                } else if (sct == 1) {
                    int ln2 = (t & 7) * 4 + ((d & 7) >> 1);
                    int j = ((d & 15) >= 8) ? 1 : 0;
                    long off = ((long)(bh * 256 + (t >> 3)) * 4 + (d >> 4)) * 64 + ln2 * 2 + j;
                    F[2*QSZ + off]       = h2u(v00, v01);
                    F[2*QSZ + off + 256] = h2u(v10, v11);
                    F[3*QSZ + off]       = h2u(flo(v00), flo(v01));
                    F[3*QSZ + off + 256] = h2u(flo(v10), flo(v11));
                } else {
                    float p00 = __shfl_xor_sync(0xffffffffu, v00, 4);
                    float p01 = __shfl_xor_sync(0xffffffffu, v01, 4);
                    float p10 = __shfl_xor_sync(0xffffffffu, v10, 4);
                    float p11 = __shfl_xor_sync(0xffffffffu, v11, 4);
                    if (!(g & 1)) {
                        int vl2 = (d & 7) * 4 + (g >> 1);
                        long off = ((long)(bh * 128 + (t >> 4)) * 8 + (d >> 3)) * 64 + vl2 * 2;
                        F[4*QSZ + off]     = h2u(v00, p00);
                        F[4*QSZ + off + 1] = h2u(v10, p10);
                        F[4*QSZ + off + 8] = h2u(v01, p01);
                        F[4*QSZ + off + 9] = h2u(v11, p11);
                        F[5*QSZ + off]     = h2u(flo(v00), flo(p00));
                        F[5*QSZ + off + 1] = h2u(flo(v10), flo(p10));
                        F[5*QSZ + off + 8] = h2u(flo(v01), flo(p01));
                        F[5*QSZ + off + 9] = h2u(flo(v11), flo(p11));
                    }
                }
            }
        }
    }
}

// ---------------- fused prologue: 4 weight packs + LN1, one kernel ----------------
__device__ __forceinline__ void do_pack_w(const float* __restrict__ W, int N,
                                          uint32_t* __restrict__ out, long idx) {
    int j = idx & 1;
    int lane = (idx >> 1) & 31;
    long rest = idx >> 6;
    int NBt = N >> 3;
    int nb = (int)(rest % NBt);
    int kc = (int)(rest / NBt);
    int n = nb * 8 + (lane >> 2);
    int k = kc * 16 + j * 8 + (lane & 3) * 2;
    out[idx] = h2u(W[(long)k * N + n], W[(long)(k + 1) * N + n]);
}

__device__ __forceinline__ void do_pack_qkv(const float* __restrict__ Wq,
                                            const float* __restrict__ Wk,
                                            const float* __restrict__ Wv,
                                            uint32_t* __restrict__ out, long idx) {
    int j = idx & 1;
    int lane = (idx >> 1) & 31;
    long rest = idx >> 6;
    int nb = (int)(rest % (E3/8));
    int kc = (int)(rest / (E3/8));
    int n = nb * 8 + (lane >> 2);
    int k = kc * 16 + j * 8 + (lane & 3) * 2;
    int s = n >> 10, rr = n & 1023, h = rr >> 6, d = rr & 63;
    const float* W = (s == 0) ? Wq : (s == 1) ? Wk : Wv;
    long o1 = (long)h * (E * HS) + (long)k * HS + d;
    out[idx] = h2u(W[o1], W[o1 + HS]);
}

__device__ __forceinline__ float block_sum_256(float v, float* red) {
    #pragma unroll
    for (int o = 16; o > 0; o >>= 1) v += __shfl_xor_sync(0xffffffffu, v, o);
    int lane = threadIdx.x & 31, w = threadIdx.x >> 5;
    if (lane == 0) red[w] = v;
    __syncthreads();
    float r = (threadIdx.x < 8) ? red[threadIdx.x] : 0.f;
    if (w == 0) {
        #pragma unroll
        for (int o = 4; o > 0; o >>= 1) r += __shfl_xor_sync(0xffu, r, o);
        if (lane == 0) red[0] = r;
    }
    __syncthreads();
    float out = red[0];
    __syncthreads();
    return out;
}

__device__ __forceinline__ void do_ln_pack(const float* __restrict__ x,
                                           const float* __restrict__ gain,
                                           const float* __restrict__ bias,
                                           uint32_t* __restrict__ o,
                                           long row, float* red) {
    int tid = threadIdx.x;
    float4 v = ((const float4*)(x + row * E))[tid];
    float mean = block_sum_256(v.x + v.y + v.z + v.w, red) * (1.0f / E);
    float dx = v.x-mean, dy = v.y-mean, dz = v.z-mean, dw = v.w-mean;
    float var = block_sum_256(dx*dx + dy*dy + dz*dz + dw*dw, red) * (1.0f/(E-1));
    float inv = 1.0f / sqrtf(var + 1e-5f);
    float4 gv = ((const float4*)gain)[tid];
    float4 bv = ((const float4*)bias)[tid];
    float r0 = dx*inv*gv.x + bv.x, r1 = dy*inv*gv.y + bv.y;
    float r2 = dz*inv*gv.z + bv.z, r3 = dw*inv*gv.w + bv.w;
    int r = (int)(row & 15);
    long mbG = row >> 4;
    int kc = tid >> 2, kk0 = (tid & 3) * 4;
    int i2 = (r >= 8 ? 1 : 0) + (kk0 >= 8 ? 2 : 0);
    int lane = (r & 7) * 4 + ((kk0 & 7) >> 1);
    long base = (mbG * 64 + kc) * 128;
    o[base + lane * 4 + i2]       = h2u(r0, r1);
    o[base + (lane + 1) * 4 + i2] = h2u(r2, r3);
}

// grid layout: [0,6144) pack_qkv | [6144,8192) pack_w(Wp) | [8192,16384) pack_w(W1)
//              | [16384,24576) pack_w(W2) | [24576,32768) LN1
__global__ __launch_bounds__(256) void prologue(
    const float* __restrict__ Wq, const float* __restrict__ Wk,
    const float* __restrict__ Wv, const float* __restrict__ Wp,
    const float* __restrict__ W1, const float* __restrict__ W2,
    const float* __restrict__ x,  const float* __restrict__ g1,
    const float* __restrict__ be1,
    uint32_t* __restrict__ wqkvB, uint32_t* __restrict__ wpB,
    uint32_t* __restrict__ w1B,   uint32_t* __restrict__ w2B,
    uint32_t* __restrict__ hA)
{
    __shared__ float red[8];
    int b = blockIdx.x;
    if (b < 6144) {
        do_pack_qkv(Wq, Wk, Wv, wqkvB, (long)b * 256 + threadIdx.x);
    } else if (b < 8192) {
        do_pack_w(Wp, E, wpB, (long)(b - 6144) * 256 + threadIdx.x);
    } else if (b < 16384) {
        do_pack_w(W1, FE, w1B, (long)(b - 8192) * 256 + threadIdx.x);
    } else if (b < 24576) {
        do_pack_w(W2, E, w2B, (long)(b - 16384) * 256 + threadIdx.x);
    } else {
        do_ln_pack(x, g1, be1, hA, (long)(b - 24576), red);
    }
}

// ---------------- standalone LN (for LN2) -----------------------------------------
__global__ void ln_pack(const float* __restrict__ x, const float* __restrict__ gain,
                        const float* __restrict__ bias, uint32_t* __restrict__ o) {
    __shared__ float red[8];
    do_ln_pack(x, gain, bias, o, (long)blockIdx.x, red);
}

// ---------------- MMA flash attention (R12 config: 64 q-rows, 4 warps) ------------
__global__ __launch_bounds__(128) void attn_mma(const uint32_t* __restrict__ pf,
                                                uint32_t* __restrict__ out) {
    const int qt = 31 - blockIdx.x;
    const int bh = blockIdx.y;
    const int ln = threadIdx.x & 31, wq = threadIdx.x >> 5;
    const int g = ln >> 2, tg = ln & 3;
    const int row0 = qt * 64 + wq * 16 + g;

    uint4 qh[4], qlo[4];
    const uint32_t* qfb = pf + ((long)(bh * 128 + qt * 4 + wq) * 4) * 128 + ln * 4;
    #pragma unroll
    for (int kc = 0; kc < 4; kc++) {
        qh[kc]  = *(const uint4*)(qfb + kc * 128);
        qlo[kc] = *(const uint4*)(qfb + QSZ + kc * 128);
    }

    float oc[8][4];
    #pragma unroll
    for (int i = 0; i < 8; i++) { oc[i][0]=oc[i][1]=oc[i][2]=oc[i][3]=0.f; }
    float m0 = -1e30f, m1 = -1e30f, l0 = 0.f, l1 = 0.f;

    for (int kt = 0; kt <= qt; kt++) {
        if (kt < qt) {
            const uint32_t* kn = pf + 2*QSZ + ((long)(bh * 256 + (kt + 1) * 8) * 4) * 64;
            const uint32_t* vn = pf + 4*QSZ + ((long)(bh * 128 + (kt + 1) * 4) * 8) * 64;
            pfl1(kn + ln * 64);            pfl1(kn + ln * 64 + 32);
            pfl1(kn + QSZ + ln * 64);      pfl1(kn + QSZ + ln * 64 + 32);
            pfl1(vn + ln * 64);            pfl1(vn + ln * 64 + 32);
            pfl1(vn + QSZ + ln * 64);      pfl1(vn + QSZ + ln * 64 + 32);
        }

        float sc[8][4];
        #pragma unroll
        for (int i = 0; i < 8; i++) { sc[i][0]=sc[i][1]=sc[i][2]=sc[i][3]=0.f; }

        const uint32_t* kfb = pf + 2*QSZ + ((long)(bh * 256 + kt * 8) * 4) * 64 + ln * 2;
        #pragma unroll
        for (int kc = 0; kc < 4; kc++)
            #pragma unroll
            for (int nt = 0; nt < 8; nt++) {
                uint2 kbh = *(const uint2*)(kfb + (nt * 4 + kc) * 64);
                uint2 kbl = *(const uint2*)(kfb + QSZ + (nt * 4 + kc) * 64);
                MMA16816(sc[nt], qh[kc],  kbh);
                MMA16816(sc[nt], qlo[kc], kbh);
                MMA16816(sc[nt], qh[kc],  kbl);
            }

        if (kt == qt) {
            #pragma unroll
            for (int nt = 0; nt < 8; nt++) {
                int c = kt * 64 + nt * 8 + tg * 2;
                sc[nt][0] = (c     > row0)     ? -1e30f : sc[nt][0] * 8.f;
                sc[nt][1] = (c + 1 > row0)     ? -1e30f : sc[nt][1] * 8.f;
                sc[nt][2] = (c     > row0 + 8) ? -1e30f : sc[nt][2] * 8.f;
                sc[nt][3] = (c + 1 > row0 + 8) ? -1e30f : sc[nt][3] * 8.f;
            }
        } else {
            #pragma unroll
            for (int nt = 0; nt < 8; nt++) {
                sc[nt][0] *= 8.f; sc[nt][1] *= 8.f; sc[nt][2] *= 8.f; sc[nt][3] *= 8.f;
            }
        }

        float mx0 = m0, mx1 = m1;
        #pragma unroll
        for (int nt = 0; nt < 8; nt++) {
            mx0 = fmaxf(mx0, fmaxf(sc[nt][0], sc[nt][1]));
            mx1 = fmaxf(mx1, fmaxf(sc[nt][2], sc[nt][3]));
        }
        mx0 = fmaxf(mx0, __shfl_xor_sync(0xffffffffu, mx0, 1));
        mx0 = fmaxf(mx0, __shfl_xor_sync(0xffffffffu, mx0, 2));
        mx1 = fmaxf(mx1, __shfl_xor_sync(0xffffffffu, mx1, 1));
        mx1 = fmaxf(mx1, __shfl_xor_sync(0xffffffffu, mx1, 2));
        float corr0 = fexp(m0 - mx0), corr1 = fexp(m1 - mx1);
        m0 = mx0; m1 = mx1;
        l0 *= corr0; l1 *= corr1;
        #pragma unroll
        for (int nt = 0; nt < 8; nt++) {
            sc[nt][0] = fexp(sc[nt][0] - mx0);
            sc[nt][1] = fexp(sc[nt][1] - mx0);
            sc[nt][2] = fexp(sc[nt][2] - mx1);
            sc[nt][3] = fexp(sc[nt][3] - mx1);
            l0 += sc[nt][0] + sc[nt][1];
            l1 += sc[nt][2] + sc[nt][3];
        }
        uint4 pah[4], pal[4];
        #pragma unroll
        for (int k2 = 0; k2 < 4; k2++) {
            pah[k2].x = h2u(sc[2*k2][0],   sc[2*k2][1]);
            pah[k2].y = h2u(sc[2*k2][2],   sc[2*k2][3]);
            pah[k2].z = h2u(sc[2*k2+1][0], sc[2*k2+1][1]);
            pah[k2].w = h2u(sc[2*k2+1][2], sc[2*k2+1][3]);
            pal[k2].x = h2u(flo(sc[2*k2][0]),   flo(sc[2*k2][1]));
            pal[k2].y = h2u(flo(sc[2*k2][2]),   flo(sc[2*k2][3]));
            pal[k2].z = h2u(flo(sc[2*k2+1][0]), flo(sc[2*k2+1][1]));
            pal[k2].w = h2u(flo(sc[2*k2+1][2]), flo(sc[2*k2+1][3]));
        }
        #pragma unroll
        for (int nbv = 0; nbv < 8; nbv++) {
            oc[nbv][0] *= corr0; oc[nbv][1] *= corr0;
            oc[nbv][2] *= corr1; oc[nbv][3] *= corr1;
        }
        const uint32_t* vfb = pf + 4*QSZ + ((long)(bh * 128 + kt * 4) * 8) * 64 + ln * 2;
        #pragma unroll
        for (int k2 = 0; k2 < 4; k2++)
            #pragma unroll
            for (int nbv = 0; nbv < 8; nbv++) {
                uint2 vbh = *(const uint2*)(vfb + (k2 * 8 + nbv) * 64);
                uint2 vbl = *(const uint2*)(vfb + QSZ + (k2 * 8 + nbv) * 64);
                MMA16816(oc[nbv], pah[k2], vbh);
                MMA16816(oc[nbv], pal[k2], vbh);
                MMA16816(oc[nbv], pah[k2], vbl);
            }
    }

    l0 += __shfl_xor_sync(0xffffffffu, l0, 1);
    l0 += __shfl_xor_sync(0xffffffffu, l0, 2);
    l1 += __shfl_xor_sync(0xffffffffu, l1, 1);
    l1 += __shfl_xor_sync(0xffffffffu, l1, 2);
    float inv0 = 1.f / l0, inv1 = 1.f / l1;

    int hloc = bh & 15;
    long mbG = (long)(bh >> 4) * 128 + qt * 4 + wq;
    #pragma unroll
    for (int nbv = 0; nbv < 8; nbv++) {
        int kco = hloc * 4 + (nbv >> 1);
        long base = (mbG * 64 + kco) * 128 + (g * 4 + tg) * 4 + ((nbv & 1) ? 2 : 0);
        out[base]     = h2u(oc[nbv][0] * inv0, oc[nbv][1] * inv0);
        out[base + 1] = h2u(oc[nbv][2] * inv1, oc[nbv][3] * inv1);
    }
}

// ---------------- launch ----------------------------------------------------------
extern "C" void kernel_launch(void* const* d_in, const int* in_sizes, int n_in,
                              void* d_out, int out_size) {
    const float* x   = (const float*)d_in[0];
    const float* Wq  = (const float*)d_in[1];
    const float* Wk  = (const float*)d_in[2];
    const float* Wv  = (const float*)d_in[3];
    const float* Wp  = (const float*)d_in[4];
    const float* bp  = (const float*)d_in[5];
    const float* W1  = (const float*)d_in[6];
    const float* b1  = (const float*)d_in[7];
    const float* W2  = (const float*)d_in[8];
    const float* b2  = (const float*)d_in[9];
    const float* g1  = (const float*)d_in[10];
    const float* be1 = (const float*)d_in[11];
    const float* g2  = (const float*)d_in[12];
    const float* be2 = (const float*)d_in[13];
    float* out = (float*)d_out;

    uint32_t *phA, *pff1A, *pfrag, *pwqkvB, *pwpB, *pw1B, *pw2B;
    float *px1;
    cudaGetSymbolAddress((void**)&phA,    g_hA);
    cudaGetSymbolAddress((void**)&pff1A,  g_ff1A);
    cudaGetSymbolAddress((void**)&pfrag,  g_frag);
    cudaGetSymbolAddress((void**)&px1,    g_x1);
    cudaGetSymbolAddress((void**)&pwqkvB, g_wqkvB);
    cudaGetSymbolAddress((void**)&pwpB,   g_wpB);
    cudaGetSymbolAddress((void**)&pw1B,   g_w1B);
    cudaGetSymbolAddress((void**)&pw2B,   g_w2B);

    // fused prologue: all weight packs + LN1 in one kernel (fully parallel)
    prologue<<<32768, 256>>>(Wq, Wk, Wv, Wp, W1, W2, x, g1, be1,
                             pwqkvB, pwpB, pw1B, pw2B, phA);
    // qkv = h @ Wqkv -> Q/K/V hi+lo fragments
    hgemm<3><<<dim3(E3/128, BT/128), 256>>>(phA, pwqkvB, nullptr, nullptr, pfrag, 64, E3, 0);
    // attention -> A-perm
    attn_mma<<<dim3(32, 64), 128>>>(pfrag, phA);
    // x1 = x + attn @ Wp + bp
    hgemm<1><<<dim3(E/128, BT/128), 256>>>(phA, pwpB, bp, x, px1, 64, E, 0);
    // LN2 -> A-perm
    ln_pack<<<BT, 256>>>(px1, g2, be2, phA);
    // ff1 = relu(h2 @ W1 + b1) -> A-perm
    hgemm<2><<<dim3(FE/128, BT/128), 256>>>(phA, pw1B, b1, nullptr, pff1A, 64, FE, 256);
    // out = x1 + ff1 @ W2 + b2
    hgemm<1><<<dim3(E/128, BT/128), 256>>>(pff1A, pw2B, b2, px1, out, 256, E, 0);
}